// round 4
// baseline (speedup 1.0000x reference)
#include <cuda_runtime.h>

#define Bn 4
#define Pn 8
#define Vn 2048
#define En 2048
#define Fn 4096
#define TILES 4
#define TPB 128              // 4 warps
#define VPT 4                // vertices per thread -> 512 verts per block
#define CHAM_BLOCKS (Bn * Pn * TILES)   // 128
#define BIGF 3.402823466e38f

__device__ float g_part_sum[CHAM_BLOCKS];
__device__ float g_part_cnt[CHAM_BLOCKS];
__device__ unsigned int g_counter;   // never reset; +CHAM_BLOCKS per launch

// ---------------------------------------------------------------------------
// packed fp32x2 helpers (sm_103a FFMA2)
// ---------------------------------------------------------------------------
__device__ __forceinline__ unsigned long long bcast2(float v) {
    unsigned long long r;
    asm("mov.b64 %0, {%1, %1};" : "=l"(r) : "f"(v));
    return r;
}

// d2[k] = px*x2[k] + py*y2[k] + c2[k]  for k=0,1 ; fold into mins
__device__ __forceinline__ void edge2(float& m0, float& m1,
                                      unsigned long long pxx, unsigned long long pyy,
                                      unsigned long long x2, unsigned long long y2,
                                      unsigned long long c2)
{
    float d0, d1;
    asm("{\n\t"
        ".reg .b64 t;\n\t"
        "fma.rn.f32x2 t, %2, %3, %4;\n\t"
        "fma.rn.f32x2 t, %5, %6, t;\n\t"
        "mov.b64 {%0, %1}, t;\n\t"
        "}"
        : "=f"(d0), "=f"(d1)
        : "l"(pyy), "l"(y2), "l"(c2), "l"(pxx), "l"(x2));
    m0 = fminf(m0, d0);
    m1 = fminf(m1, d1);
}

// ---------------------------------------------------------------------------
// Single fused kernel. Blocks [0, 128): chamfer. Blocks [128, 132): volume.
// One block per SM, single wave. Last chamfer block finalizes.
// ---------------------------------------------------------------------------
__global__ void __launch_bounds__(TPB)
fused_kernel(const float* __restrict__ xs,
             const float* __restrict__ pm,
             const float* __restrict__ em,
             const int*   __restrict__ lens,
             const void*  __restrict__ bmask,
             const int*   __restrict__ faces,
             const float* __restrict__ tv,
             float* __restrict__ out)
{
    const int bx  = blockIdx.x;
    const int tid = threadIdx.x;

    // =========================== VOLUME BLOCKS ============================
    if (bx >= CHAM_BLOCKS) {
        __shared__ double sred[TPB];
        const int b = bx - CHAM_BLOCKS;
        const float* base = xs + (size_t)b * Vn * 3;
        double acc = 0.0;
        for (int f = tid; f < Fn; f += TPB) {
            const int* fi = faces + ((size_t)b * Fn + f) * 3;
            const float* a0 = base + (size_t)fi[0] * 3;
            const float* a1 = base + (size_t)fi[1] * 3;
            const float* a2 = base + (size_t)fi[2] * 3;
            const float v0x = a0[0], v0y = a0[1], v0z = a0[2];
            const float v1x = a1[0], v1y = a1[1], v1z = a1[2];
            const float v2x = a2[0], v2y = a2[1], v2z = a2[2];
            const float cx = v0y * v1z - v0z * v1y;
            const float cy = v0z * v1x - v0x * v1z;
            const float cz = v0x * v1y - v0y * v1x;
            acc += (double)((cx * v2x + cy * v2y + cz * v2z) * (1.0f / 6.0f));
        }
        sred[tid] = acc;
        __syncthreads();
        #pragma unroll
        for (int s = TPB / 2; s >= 1; s >>= 1) {
            if (tid < s) sred[tid] += sred[tid + s];
            __syncthreads();
        }
        if (tid == 0) {
            float vols = fabsf((float)sred[0]);
            float d = vols - tv[b];
            out[4 + b] = d * d;
        }
        return;
    }

    // =========================== CHAMFER BLOCKS ===========================
    // edge table SoA: c = |e|^2, x = -2ex, y = -2ey  (16B-aligned for LDS.128)
    __shared__ __align__(16) float s_c[En];
    __shared__ __align__(16) float s_x[En];
    __shared__ __align__(16) float s_y[En];
    __shared__ float  s_rs[TPB / 32], s_rc[TPB / 32];
    __shared__ int    s_last;

    const int tile = bx & (TILES - 1);
    const int p    = (bx >> 2) & (Pn - 1);
    const int b    = bx >> 5;

    // ---- preload + transform edge table (pairs of edges per float4) ----
    const float4* embase4 = (const float4*)(em + ((size_t)(b * Pn + p)) * En * 2);
    float2* c2p = (float2*)s_c;
    float2* x2p = (float2*)s_x;
    float2* y2p = (float2*)s_y;
    #pragma unroll
    for (int i = tid; i < En / 2; i += TPB) {
        float4 e4 = embase4[i];                 // ex0, ey0, ex1, ey1
        c2p[i] = make_float2(fmaf(e4.x, e4.x, e4.y * e4.y),
                             fmaf(e4.z, e4.z, e4.w * e4.w));
        x2p[i] = make_float2(-2.0f * e4.x, -2.0f * e4.z);
        y2p[i] = make_float2(-2.0f * e4.y, -2.0f * e4.w);
    }

    // ---- boundary_mask layout detection (first 4KB) ----
    // int32-widened bool: every byte at offset %4 != 0 is zero
    unsigned int scan = 0;
    {
        const unsigned int* mw = (const unsigned int*)bmask;
        #pragma unroll
        for (int i = tid; i < 1024; i += TPB)
            scan |= (mw[i] & 0xFFFFFF00u);
    }
    const int mask_is_bytes = __syncthreads_or(scan != 0);  // also the preload barrier

    // ---- per-thread vertex projections (VPT verts, stride TPB) ----
    const float* M = pm + p * 12;
    const int vbase = tile * (TPB * VPT);
    float px[VPT], py[VPT], ppv[VPT];
    unsigned long long pxx[VPT], pyy[VPT];
    #pragma unroll
    for (int j = 0; j < VPT; ++j) {
        const int v = vbase + j * TPB + tid;
        const float* xv = xs + ((size_t)b * Vn + v) * 3;
        const float x = xv[0], y = xv[1], z = xv[2];
        const float q0 = M[0] * x + M[1] * y + M[2]  * z + M[3];
        const float q1 = M[4] * x + M[5] * y + M[6]  * z + M[7];
        const float q2 = M[8] * x + M[9] * y + M[10] * z + M[11];
        px[j] = q0 / q2;
        py[j] = q1 / q2;
        ppv[j] = fmaf(px[j], px[j], py[j] * py[j]);
        pxx[j] = bcast2(px[j]);
        pyy[j] = bcast2(py[j]);
    }

    // ---- main loop: 4 edges x 4 verts per iteration (3x LDS.128 broadcast) ----
    const int L  = lens[b * Pn + p];
    const int P4 = L >> 2;
    float ma[VPT], mb[VPT], mc[VPT], md[VPT];
    #pragma unroll
    for (int j = 0; j < VPT; ++j) { ma[j] = BIGF; mb[j] = BIGF; mc[j] = BIGF; md[j] = BIGF; }

    const ulonglong2* pc = (const ulonglong2*)s_c;
    const ulonglong2* pxv = (const ulonglong2*)s_x;
    const ulonglong2* pyv = (const ulonglong2*)s_y;

    #pragma unroll 2
    for (int i = 0; i < P4; ++i) {
        const ulonglong2 c4 = pc[i];
        const ulonglong2 x4 = pxv[i];
        const ulonglong2 y4 = pyv[i];
        #pragma unroll
        for (int j = 0; j < VPT; ++j) {
            edge2(ma[j], mb[j], pxx[j], pyy[j], x4.x, y4.x, c4.x);
            edge2(mc[j], md[j], pxx[j], pyy[j], x4.y, y4.y, c4.y);
        }
    }
    for (int e = P4 * 4; e < L; ++e) {      // 0..3 trailing edges
        const float c = s_c[e], xx = s_x[e], yy = s_y[e];
        #pragma unroll
        for (int j = 0; j < VPT; ++j)
            ma[j] = fminf(ma[j], fmaf(px[j], xx, fmaf(py[j], yy, c)));
    }

    // ---- combine + boundary mask + local accumulation ----
    float cs = 0.0f, cc = 0.0f;
    #pragma unroll
    for (int j = 0; j < VPT; ++j) {
        const float dmin = fminf(fminf(ma[j], mb[j]), fminf(mc[j], md[j])) + ppv[j];
        const int v = vbase + j * TPB + tid;
        const int midx = (b * Pn + p) * Vn + v;
        float w;
        if (mask_is_bytes) w = (((const unsigned char*)bmask)[midx] != 0) ? 1.0f : 0.0f;
        else               w = (((const int*)bmask)[midx] != 0) ? 1.0f : 0.0f;
        cs = fmaf(w, dmin, cs);
        cc += w;
    }

    // ---- block reduction (deterministic fixed tree) ----
    #pragma unroll
    for (int off = 16; off >= 1; off >>= 1) {
        cs += __shfl_down_sync(0xffffffffu, cs, off);
        cc += __shfl_down_sync(0xffffffffu, cc, off);
    }
    const int wid = tid >> 5;
    if ((tid & 31) == 0) { s_rs[wid] = cs; s_rc[wid] = cc; }
    __syncthreads();

    if (tid == 0) {
        float ts = 0.0f, tc = 0.0f;
        #pragma unroll
        for (int i = 0; i < TPB / 32; ++i) { ts += s_rs[i]; tc += s_rc[i]; }
        const int slot = ((b * Pn + p) * TILES) + tile;
        g_part_sum[slot] = ts;
        g_part_cnt[slot] = tc;
        __threadfence();
        unsigned int old = atomicAdd(&g_counter, 1u);
        s_last = (((old + 1u) & (CHAM_BLOCKS - 1u)) == 0u) ? 1 : 0;
    }
    __syncthreads();

    // ---- last block finalizes chamfer means ----
    if (s_last && tid < 32) {
        __threadfence();
        const int lane = tid;                    // lane = b*Pn + p
        float s = 0.0f, c = 0.0f;
        #pragma unroll
        for (int t = 0; t < TILES; ++t) {
            s += g_part_sum[lane * TILES + t];
            c += g_part_cnt[lane * TILES + t];
        }
        float ppj = s / fmaxf(c, 1.0f);
        #pragma unroll
        for (int off = 4; off >= 1; off >>= 1)
            ppj += __shfl_down_sync(0xffffffffu, ppj, off, 8);
        if ((lane & 7) == 0) out[lane >> 3] = ppj * (1.0f / Pn);
    }
}

// ---------------------------------------------------------------------------
extern "C" void kernel_launch(void* const* d_in, const int* in_sizes, int n_in,
                              void* d_out, int out_size)
{
    const float* xs    = (const float*)d_in[0];   // (4,2048,3)
    const float* pm    = (const float*)d_in[1];   // (8,3,4)
    const float* em    = (const float*)d_in[2];   // (4,8,2048,2)
    const int*   lens  = (const int*)  d_in[3];   // (4,8)
    const void*  bmask =               d_in[4];   // (4,8,2048) bool (layout auto-detected)
    const int*   faces = (const int*)  d_in[5];   // (4,4096,3)
    const float* tv    = (const float*)d_in[6];   // (4,)
    float* out = (float*)d_out;                   // [chamfer(4), vol_error(4)]

    fused_kernel<<<CHAM_BLOCKS + Bn, TPB>>>(xs, pm, em, lens, bmask, faces, tv, out);
}

// round 5
// speedup vs baseline: 1.2885x; 1.2885x over previous
#include <cuda_runtime.h>

#define Bn 4
#define Pn 8
#define Vn 2048
#define En 2048
#define Fn 4096
#define TILES 4
#define TPB 256              // 8 warps -> 2 warps per SMSP
#define VPT 2                // vertices per thread -> 512 verts per block
#define CHAM_BLOCKS (Bn * Pn * TILES)   // 128
#define BIGF 3.402823466e38f

__device__ float g_part_sum[CHAM_BLOCKS];
__device__ float g_part_cnt[CHAM_BLOCKS];
__device__ unsigned int g_counter;   // never reset; +CHAM_BLOCKS per launch

// ---------------------------------------------------------------------------
// packed fp32x2 helpers (sm_103a FFMA2)
// ---------------------------------------------------------------------------
__device__ __forceinline__ unsigned long long bcast2(float v) {
    unsigned long long r;
    asm("mov.b64 %0, {%1, %1};" : "=l"(r) : "f"(v));
    return r;
}

// d2[k] = px*x2[k] + py*y2[k] + c2[k]  for k=0,1 ; fold into mins
__device__ __forceinline__ void edge2(float& m0, float& m1,
                                      unsigned long long pxx, unsigned long long pyy,
                                      unsigned long long x2, unsigned long long y2,
                                      unsigned long long c2)
{
    float d0, d1;
    asm("{\n\t"
        ".reg .b64 t;\n\t"
        "fma.rn.f32x2 t, %2, %3, %4;\n\t"
        "fma.rn.f32x2 t, %5, %6, t;\n\t"
        "mov.b64 {%0, %1}, t;\n\t"
        "}"
        : "=f"(d0), "=f"(d1)
        : "l"(pyy), "l"(y2), "l"(c2), "l"(pxx), "l"(x2));
    m0 = fminf(m0, d0);
    m1 = fminf(m1, d1);
}

// ---------------------------------------------------------------------------
// Single fused kernel. Blocks [0, 128): chamfer. Blocks [128, 132): volume.
// One block per SM, single wave, 2 warps per SMSP. Last chamfer block finalizes.
// ---------------------------------------------------------------------------
__global__ void __launch_bounds__(TPB)
fused_kernel(const float* __restrict__ xs,
             const float* __restrict__ pm,
             const float* __restrict__ em,
             const int*   __restrict__ lens,
             const void*  __restrict__ bmask,
             const int*   __restrict__ faces,
             const float* __restrict__ tv,
             float* __restrict__ out)
{
    const int bx  = blockIdx.x;
    const int tid = threadIdx.x;

    // =========================== VOLUME BLOCKS ============================
    if (bx >= CHAM_BLOCKS) {
        __shared__ double sred[TPB];
        const int b = bx - CHAM_BLOCKS;
        const float* base = xs + (size_t)b * Vn * 3;
        double acc = 0.0;
        for (int f = tid; f < Fn; f += TPB) {
            const int* fi = faces + ((size_t)b * Fn + f) * 3;
            const float* a0 = base + (size_t)fi[0] * 3;
            const float* a1 = base + (size_t)fi[1] * 3;
            const float* a2 = base + (size_t)fi[2] * 3;
            const float v0x = a0[0], v0y = a0[1], v0z = a0[2];
            const float v1x = a1[0], v1y = a1[1], v1z = a1[2];
            const float v2x = a2[0], v2y = a2[1], v2z = a2[2];
            const float cx = v0y * v1z - v0z * v1y;
            const float cy = v0z * v1x - v0x * v1z;
            const float cz = v0x * v1y - v0y * v1x;
            acc += (double)((cx * v2x + cy * v2y + cz * v2z) * (1.0f / 6.0f));
        }
        sred[tid] = acc;
        __syncthreads();
        #pragma unroll
        for (int s = TPB / 2; s >= 1; s >>= 1) {
            if (tid < s) sred[tid] += sred[tid + s];
            __syncthreads();
        }
        if (tid == 0) {
            float vols = fabsf((float)sred[0]);
            float d = vols - tv[b];
            out[4 + b] = d * d;
        }
        return;
    }

    // =========================== CHAMFER BLOCKS ===========================
    // edge table SoA: c = |e|^2, x = -2ex, y = -2ey  (16B-aligned for LDS.128)
    __shared__ __align__(16) float s_c[En];
    __shared__ __align__(16) float s_x[En];
    __shared__ __align__(16) float s_y[En];
    __shared__ float  s_rs[TPB / 32], s_rc[TPB / 32];
    __shared__ int    s_last;

    const int tile = bx & (TILES - 1);
    const int p    = (bx >> 2) & (Pn - 1);
    const int b    = bx >> 5;

    // ---- preload + transform edge table (pairs of edges per float4) ----
    const float4* embase4 = (const float4*)(em + ((size_t)(b * Pn + p)) * En * 2);
    float2* c2p = (float2*)s_c;
    float2* x2p = (float2*)s_x;
    float2* y2p = (float2*)s_y;
    #pragma unroll
    for (int i = tid; i < En / 2; i += TPB) {
        float4 e4 = embase4[i];                 // ex0, ey0, ex1, ey1
        c2p[i] = make_float2(fmaf(e4.x, e4.x, e4.y * e4.y),
                             fmaf(e4.z, e4.z, e4.w * e4.w));
        x2p[i] = make_float2(-2.0f * e4.x, -2.0f * e4.z);
        y2p[i] = make_float2(-2.0f * e4.y, -2.0f * e4.w);
    }

    // ---- boundary_mask layout detection (first 4KB) ----
    // int32-widened bool: every byte at offset %4 != 0 is zero
    unsigned int scan = 0;
    {
        const unsigned int* mw = (const unsigned int*)bmask;
        #pragma unroll
        for (int i = tid; i < 1024; i += TPB)
            scan |= (mw[i] & 0xFFFFFF00u);
    }
    const int mask_is_bytes = __syncthreads_or(scan != 0);  // also the preload barrier

    // ---- per-thread vertex projections (VPT verts, stride TPB) ----
    const float* M = pm + p * 12;
    const int vbase = tile * (TPB * VPT);
    float px[VPT], py[VPT], ppv[VPT];
    unsigned long long pxx[VPT], pyy[VPT];
    #pragma unroll
    for (int j = 0; j < VPT; ++j) {
        const int v = vbase + j * TPB + tid;
        const float* xv = xs + ((size_t)b * Vn + v) * 3;
        const float x = xv[0], y = xv[1], z = xv[2];
        const float q0 = M[0] * x + M[1] * y + M[2]  * z + M[3];
        const float q1 = M[4] * x + M[5] * y + M[6]  * z + M[7];
        const float q2 = M[8] * x + M[9] * y + M[10] * z + M[11];
        px[j] = q0 / q2;
        py[j] = q1 / q2;
        ppv[j] = fmaf(px[j], px[j], py[j] * py[j]);
        pxx[j] = bcast2(px[j]);
        pyy[j] = bcast2(py[j]);
    }

    // ---- main loop: 4 edges x 2 verts per iteration, double-buffered LDS ----
    const int L  = lens[b * Pn + p];
    const int P4 = L >> 2;
    float ma[VPT], mb[VPT], mc[VPT], md[VPT];
    #pragma unroll
    for (int j = 0; j < VPT; ++j) { ma[j] = BIGF; mb[j] = BIGF; mc[j] = BIGF; md[j] = BIGF; }

    const ulonglong2* pc  = (const ulonglong2*)s_c;
    const ulonglong2* pxv = (const ulonglong2*)s_x;
    const ulonglong2* pyv = (const ulonglong2*)s_y;

    if (P4 > 0) {
        ulonglong2 c4 = pc[0], x4 = pxv[0], y4 = pyv[0];
        #pragma unroll 2
        for (int i = 1; i < P4; ++i) {
            const ulonglong2 cn = pc[i];
            const ulonglong2 xn = pxv[i];
            const ulonglong2 yn = pyv[i];
            #pragma unroll
            for (int j = 0; j < VPT; ++j) {
                edge2(ma[j], mb[j], pxx[j], pyy[j], x4.x, y4.x, c4.x);
                edge2(mc[j], md[j], pxx[j], pyy[j], x4.y, y4.y, c4.y);
            }
            c4 = cn; x4 = xn; y4 = yn;
        }
        #pragma unroll
        for (int j = 0; j < VPT; ++j) {
            edge2(ma[j], mb[j], pxx[j], pyy[j], x4.x, y4.x, c4.x);
            edge2(mc[j], md[j], pxx[j], pyy[j], x4.y, y4.y, c4.y);
        }
    }
    for (int e = P4 * 4; e < L; ++e) {      // 0..3 trailing edges
        const float c = s_c[e], xx = s_x[e], yy = s_y[e];
        #pragma unroll
        for (int j = 0; j < VPT; ++j)
            ma[j] = fminf(ma[j], fmaf(px[j], xx, fmaf(py[j], yy, c)));
    }

    // ---- combine + boundary mask + local accumulation ----
    float cs = 0.0f, cc = 0.0f;
    #pragma unroll
    for (int j = 0; j < VPT; ++j) {
        const float dmin = fminf(fminf(ma[j], mb[j]), fminf(mc[j], md[j])) + ppv[j];
        const int v = vbase + j * TPB + tid;
        const int midx = (b * Pn + p) * Vn + v;
        float w;
        if (mask_is_bytes) w = (((const unsigned char*)bmask)[midx] != 0) ? 1.0f : 0.0f;
        else               w = (((const int*)bmask)[midx] != 0) ? 1.0f : 0.0f;
        cs = fmaf(w, dmin, cs);
        cc += w;
    }

    // ---- block reduction (deterministic fixed tree) ----
    #pragma unroll
    for (int off = 16; off >= 1; off >>= 1) {
        cs += __shfl_down_sync(0xffffffffu, cs, off);
        cc += __shfl_down_sync(0xffffffffu, cc, off);
    }
    const int wid = tid >> 5;
    if ((tid & 31) == 0) { s_rs[wid] = cs; s_rc[wid] = cc; }
    __syncthreads();

    if (tid == 0) {
        float ts = 0.0f, tc = 0.0f;
        #pragma unroll
        for (int i = 0; i < TPB / 32; ++i) { ts += s_rs[i]; tc += s_rc[i]; }
        const int slot = ((b * Pn + p) * TILES) + tile;
        g_part_sum[slot] = ts;
        g_part_cnt[slot] = tc;
        __threadfence();
        unsigned int old = atomicAdd(&g_counter, 1u);
        s_last = (((old + 1u) & (CHAM_BLOCKS - 1u)) == 0u) ? 1 : 0;
    }
    __syncthreads();

    // ---- last block finalizes chamfer means ----
    if (s_last && tid < 32) {
        __threadfence();
        const int lane = tid;                    // lane = b*Pn + p
        float s = 0.0f, c = 0.0f;
        #pragma unroll
        for (int t = 0; t < TILES; ++t) {
            s += g_part_sum[lane * TILES + t];
            c += g_part_cnt[lane * TILES + t];
        }
        float ppj = s / fmaxf(c, 1.0f);
        #pragma unroll
        for (int off = 4; off >= 1; off >>= 1)
            ppj += __shfl_down_sync(0xffffffffu, ppj, off, 8);
        if ((lane & 7) == 0) out[lane >> 3] = ppj * (1.0f / Pn);
    }
}

// ---------------------------------------------------------------------------
extern "C" void kernel_launch(void* const* d_in, const int* in_sizes, int n_in,
                              void* d_out, int out_size)
{
    const float* xs    = (const float*)d_in[0];   // (4,2048,3)
    const float* pm    = (const float*)d_in[1];   // (8,3,4)
    const float* em    = (const float*)d_in[2];   // (4,8,2048,2)
    const int*   lens  = (const int*)  d_in[3];   // (4,8)
    const void*  bmask =               d_in[4];   // (4,8,2048) bool (layout auto-detected)
    const int*   faces = (const int*)  d_in[5];   // (4,4096,3)
    const float* tv    = (const float*)d_in[6];   // (4,)
    float* out = (float*)d_out;                   // [chamfer(4), vol_error(4)]

    fused_kernel<<<CHAM_BLOCKS + Bn, TPB>>>(xs, pm, em, lens, bmask, faces, tv, out);
}